// round 3
// baseline (speedup 1.0000x reference)
#include <cuda_runtime.h>
#include <cstdint>

typedef unsigned long long u64;
typedef unsigned int u32;

// ---------------- problem constants ----------------
#define BB 8
#define CC 256
#define NPOS 21824              // per-image positions across 5 maps
#define NANCH 196416            // NPOS * 9
#define NKEY 196608             // 48 * 4096 (padded)
#define KSEL 300
#define NCHUNK 48               // stage1 chunks of 4096 per image
#define NCAND (NCHUNK * KSEL)   // 14400 candidates per image

__device__ __constant__ int c_off[6] = {0, 16384, 20480, 21504, 21760, 21824};

// ---------------- device scratch ----------------
__device__ float g_relu[(size_t)174592 * 256];   // 8*21824 positions, NCHW per (b,map)
__device__ float g_wT[256 * 9 * 256];            // [ic][tap][oc]
__device__ u64   g_keys[(size_t)BB * NKEY];
__device__ u64   g_cand[(size_t)BB * NCAND];
__device__ int   g_sel[BB * KSEL];

// ---------------- f32x2 helpers ----------------
__device__ __forceinline__ u64 pack2(float x, float y) {
    u64 r; asm("mov.b64 %0,{%1,%2};" : "=l"(r) : "f"(x), "f"(y)); return r;
}
__device__ __forceinline__ u64 dup2(float x) {
    u64 r; asm("mov.b64 %0,{%1,%1};" : "=l"(r) : "f"(x)); return r;
}
__device__ __forceinline__ void ffma2(u64 &c, u64 a, u64 b) {
    asm("fma.rn.f32x2 %0,%1,%2,%3;" : "=l"(c) : "l"(a), "l"(b), "l"(c));
}
__device__ __forceinline__ void fadd2(u64 &c, u64 a) {
    asm("add.rn.f32x2 %0,%1,%2;" : "=l"(c) : "l"(c), "l"(a));
}
__device__ __forceinline__ float2 unpack2(u64 v) {
    float2 f; asm("mov.b64 {%0,%1},%2;" : "=f"(f.x), "=f"(f.y) : "l"(v)); return f;
}

// ---------------- kernel 0: weight transpose [oc][ic][t] -> [ic][t][oc] ----------------
__global__ void k_wtrans(const float* __restrict__ w_pre) {
    int i = blockIdx.x * 1024 + threadIdx.x;
    if (i >= 256 * 9 * 256) return;
    int oc = i & 255;
    int rest = i >> 8;
    int tap = rest % 9;
    int ic = rest / 9;
    g_wT[i] = w_pre[(oc * 256 + ic) * 9 + tap];
}

// ---------------- kernel 1: conv3x3 + bias + relu (fp32, two-level accumulation) ----------
// Block: 8x8 spatial tile x 128 out channels (z selects oc half). 256 threads.
// Thread: 2x2 positions (2 horizontal f32x2 pairs) x 8 out channels.
// Accumulation: per-cc-chunk (8 ic * 9 taps = 72 terms) into ch[], folded into acc[]
// once per chunk -> ~6x lower rounding error than a single linear chain.
__global__ void __launch_bounds__(256)
k_conv(const float* __restrict__ fm, const float* __restrict__ b_pre,
       int s, int HW, int posOff) {
    extern __shared__ float sm[];
    float* in_s = sm;             // 8*10*12 = 960 floats
    float* w_s  = sm + 960;       // 8*9*128 = 9216 floats

    const int tid = threadIdx.x;
    const int tilesX = s >> 3;
    const int ty0 = (blockIdx.x / tilesX) << 3;
    const int tx0 = (blockIdx.x % tilesX) << 3;
    const int b = blockIdx.y;
    const int zh = blockIdx.z;            // oc half: 0 or 1

    const int pg = tid & 15;
    const int og = tid >> 4;              // 0..15 -> oc = zh*128 + og*8 + j
    const int py = (pg >> 2) << 1;        // 0,2,4,6
    const int px = (pg & 3) << 1;         // 0,2,4,6

    const float* fmB = fm + (size_t)b * 256 * HW;

    u64 acc[2][8];
#pragma unroll
    for (int r = 0; r < 2; ++r)
#pragma unroll
        for (int j = 0; j < 8; ++j) acc[r][j] = 0ull;

    for (int cc = 0; cc < 32; ++cc) {
        __syncthreads();
        // input tile (10x10 halo) for 8 input channels
        const float* fsrc = fmB + (size_t)(cc * 8) * HW;
        for (int idx = tid; idx < 800; idx += 256) {
            int ic = idx / 100;
            int rem = idx - ic * 100;
            int r = rem / 10;
            int c = rem - 10 * r;
            int gy = ty0 - 1 + r, gx = tx0 - 1 + c;
            float v = 0.f;
            if (gy >= 0 && gy < s && gx >= 0 && gx < s)
                v = fsrc[ic * HW + gy * s + gx];
            in_s[(ic * 10 + r) * 12 + c] = v;
        }
        // weight chunk [8ic][9tap][128oc] (this z-half), float4 copies
        {
            float4* wdst = (float4*)w_s;
            const float4* wbase = (const float4*)g_wT;
            for (int i = tid; i < 2304; i += 256) {           // 8*9*32 float4
                int icL = i / 288;
                int rem = i - icL * 288;
                int tap = rem >> 5;
                int q = rem & 31;
                wdst[i] = wbase[(((size_t)(cc * 8 + icL) * 9 + tap) << 6) + (zh << 5) + q];
            }
        }
        __syncthreads();

        // chunk accumulators (72 terms each)
        u64 ch[2][8];
#pragma unroll
        for (int r = 0; r < 2; ++r)
#pragma unroll
            for (int j = 0; j < 8; ++j) ch[r][j] = 0ull;

#pragma unroll
        for (int ic = 0; ic < 8; ++ic) {
            const float* ib = in_s + (ic * 10 + py) * 12 + px;
            u64 pr[4][3];
#pragma unroll
            for (int r = 0; r < 4; ++r) {
                float2 f01 = *(const float2*)(ib + r * 12);
                float2 f23 = *(const float2*)(ib + r * 12 + 2);
                pr[r][0] = pack2(f01.x, f01.y);
                pr[r][1] = pack2(f01.y, f23.x);
                pr[r][2] = pack2(f23.x, f23.y);
            }
            const float* wb = w_s + ic * 9 * 128 + og * 8;
#pragma unroll
            for (int tap = 0; tap < 9; ++tap) {
                const int dy = tap / 3, dx = tap - 3 * (tap / 3);
                float4 w0 = *(const float4*)(wb + tap * 128);
                float4 w1 = *(const float4*)(wb + tap * 128 + 4);
                float wv[8] = {w0.x, w0.y, w0.z, w0.w, w1.x, w1.y, w1.z, w1.w};
#pragma unroll
                for (int j = 0; j < 8; ++j) {
                    u64 wd = dup2(wv[j]);
                    ffma2(ch[0][j], pr[dy][dx], wd);
                    ffma2(ch[1][j], pr[dy + 1][dx], wd);
                }
            }
        }
        // fold chunk into master
#pragma unroll
        for (int r = 0; r < 2; ++r)
#pragma unroll
            for (int j = 0; j < 8; ++j) fadd2(acc[r][j], ch[r][j]);
    }

    // epilogue: bias + relu -> g_relu NCHW per (b,map)
    float* outB = g_relu + ((size_t)b * NPOS + posOff) * 256;
#pragma unroll
    for (int orow = 0; orow < 2; ++orow) {
        int gy = ty0 + py + orow;
        int gx = tx0 + px;
#pragma unroll
        for (int j = 0; j < 8; ++j) {
            int oc = zh * 128 + og * 8 + j;
            float2 v = unpack2(acc[orow][j]);
            float bb = b_pre[oc];
            v.x = fmaxf(v.x + bb, 0.f);
            v.y = fmaxf(v.y + bb, 0.f);
            *(float2*)(outB + (size_t)oc * HW + gy * s + gx) = v;
        }
    }
}

// ---------------- kernel 2: 1x1 proj -> sigmoid -> sortable keys ----------------
__global__ void __launch_bounds__(256)
k_proj(const float* __restrict__ w_proj, const float* __restrict__ b_proj) {
    __shared__ float ws[9 * 256];
    const int tid = threadIdx.x;
    for (int i = tid; i < 2304; i += 256) ws[i] = w_proj[i];
    __syncthreads();

    const int b = blockIdx.y;
    const int p = blockIdx.x * 256 + tid;

    if (blockIdx.x == 0 && tid < (NKEY - NANCH))
        g_keys[(size_t)b * NKEY + NANCH + tid] = 0ull;
    if (p >= NPOS) return;

    int m, hw, HW;
    if (p < 16384)      { m = 0; hw = p;         HW = 16384; }
    else if (p < 20480) { m = 1; hw = p - 16384; HW = 4096;  }
    else if (p < 21504) { m = 2; hw = p - 20480; HW = 1024;  }
    else if (p < 21760) { m = 3; hw = p - 21504; HW = 256;   }
    else                { m = 4; hw = p - 21760; HW = 64;    }
    const int off = c_off[m];

    const float* rb = g_relu + ((size_t)b * NPOS + off) * 256 + hw;
    float sum[9];
#pragma unroll
    for (int a = 0; a < 9; ++a) sum[a] = 0.f;
    // two-level accumulation: 32-term chunks
    for (int c0 = 0; c0 < 256; c0 += 32) {
        float cs[9];
#pragma unroll
        for (int a = 0; a < 9; ++a) cs[a] = 0.f;
        for (int c = c0; c < c0 + 32; ++c) {
            float v = rb[(size_t)c * HW];
#pragma unroll
            for (int a = 0; a < 9; ++a) cs[a] += v * ws[a * 256 + c];
        }
#pragma unroll
        for (int a = 0; a < 9; ++a) sum[a] += cs[a];
    }
    u64* kb = g_keys + (size_t)b * NKEY + (size_t)p * 9;
#pragma unroll
    for (int a = 0; a < 9; ++a) {
        float logit = sum[a] + b_proj[a];
        float prob = 1.0f / (1.0f + expf(-logit));
        u32 pb = __float_as_uint(prob);                 // prob>0 => bit-monotonic
        u32 idx = (u32)(p * 9 + a);
        kb[a] = ((u64)pb << 32) | (u64)(0xFFFFFFFFu - idx);  // tie -> lower idx first
    }
}

// ---------------- bitonic helpers (descending) ----------------
__device__ __forceinline__ void bitonic_step(u64* sk, int i, int j, int k) {
    int ixj = i | j;
    u64 a = sk[i], b = sk[ixj];
    bool dir = ((i & k) == 0);
    bool sw = dir ? (a < b) : (a > b);
    if (sw) { sk[i] = b; sk[ixj] = a; }
}

// ---------------- kernel 3: stage1 — sort each 4096 chunk, keep top 300 ----------------
__global__ void __launch_bounds__(512)
k_top1() {
    __shared__ u64 sk[4096];
    const int tid = threadIdx.x;
    const int blk = blockIdx.x;
    const int b = blockIdx.y;
    const u64* src = g_keys + (size_t)b * NKEY + (size_t)blk * 4096;
    for (int i = tid; i < 4096; i += 512) sk[i] = src[i];
    for (int k = 2; k <= 4096; k <<= 1) {
        for (int j = k >> 1; j > 0; j >>= 1) {
            __syncthreads();
            for (int t = tid; t < 2048; t += 512) {
                int i = ((t & ~(j - 1)) << 1) | (t & (j - 1));
                bitonic_step(sk, i, j, k);
            }
        }
    }
    __syncthreads();
    u64* dst = g_cand + ((size_t)b * NCHUNK + blk) * KSEL;
    for (int i = tid; i < KSEL; i += 512) dst[i] = sk[i];
}

// ---------------- kernel 4: stage2 — merge 14400 candidates per image ----------------
__global__ void __launch_bounds__(1024)
k_top2() {
    extern __shared__ u64 sk2[];   // 16384 keys = 128KB
    const int tid = threadIdx.x;
    const int b = blockIdx.x;
    const u64* src = g_cand + (size_t)b * NCAND;
    for (int i = tid; i < 16384; i += 1024) sk2[i] = (i < NCAND) ? src[i] : 0ull;
    for (int k = 2; k <= 16384; k <<= 1) {
        for (int j = k >> 1; j > 0; j >>= 1) {
            __syncthreads();
            for (int t = tid; t < 8192; t += 1024) {
                int i = ((t & ~(j - 1)) << 1) | (t & (j - 1));
                bitonic_step(sk2, i, j, k);
            }
        }
    }
    __syncthreads();
    if (tid < KSEL)
        g_sel[b * KSEL + tid] = (int)(0xFFFFFFFFu - (u32)(sk2[tid] & 0xFFFFFFFFull));
}

// ---------------- kernel 5: gather features + per-anchor 256x256 matvec ----------------
__global__ void __launch_bounds__(256)
k_post(const float* __restrict__ fm0, const float* __restrict__ fm1,
       const float* __restrict__ fm2, const float* __restrict__ fm3,
       const float* __restrict__ fm4, const float* __restrict__ w_post,
       const float* __restrict__ b_post, float* __restrict__ out) {
    __shared__ float x[256];
    const int n = blockIdx.x;
    const int tid = threadIdx.x;
    const int b = n / KSEL;
    const int anchor = g_sel[n];
    const int pos = anchor / 9;
    const int a = anchor - 9 * (anchor / 9);

    int m, hw, HW;
    if (pos < 16384)      { m = 0; hw = pos;         HW = 16384; }
    else if (pos < 20480) { m = 1; hw = pos - 16384; HW = 4096;  }
    else if (pos < 21504) { m = 2; hw = pos - 20480; HW = 1024;  }
    else if (pos < 21760) { m = 3; hw = pos - 21504; HW = 256;   }
    else                  { m = 4; hw = pos - 21760; HW = 64;    }
    const float* fm = (m == 0) ? fm0 : (m == 1) ? fm1 : (m == 2) ? fm2 : (m == 3) ? fm3 : fm4;

    x[tid] = fm[((size_t)b * 256 + tid) * HW + hw];
    __syncthreads();

    const float* W = w_post + (size_t)a * 65536;
    float accv = b_post[a * 256 + tid];
#pragma unroll 8
    for (int d = 0; d < 256; ++d)
        accv += x[d] * W[d * 256 + tid];
    out[(size_t)n * 256 + tid] = accv;
}

// ---------------- launch ----------------
extern "C" void kernel_launch(void* const* d_in, const int* in_sizes, int n_in,
                              void* d_out, int out_size) {
    const float* fm[5];
    for (int i = 0; i < 5; ++i) fm[i] = (const float*)d_in[i];
    const float* w_pre  = (const float*)d_in[5];
    const float* b_pre  = (const float*)d_in[6];
    const float* w_proj = (const float*)d_in[7];
    const float* b_proj = (const float*)d_in[8];
    const float* w_post = (const float*)d_in[9];
    const float* b_post = (const float*)d_in[10];
    float* out = (float*)d_out;

    static const int sidesA[5] = {128, 64, 32, 16, 8};
    static const int HWsA[5] = {16384, 4096, 1024, 256, 64};
    static const int offsA[5] = {0, 16384, 20480, 21504, 21760};

    const int convSmem = (960 + 9216) * 4;   // 40704 B
    cudaFuncSetAttribute(k_conv, cudaFuncAttributeMaxDynamicSharedMemorySize, convSmem);
    cudaFuncSetAttribute(k_top2, cudaFuncAttributeMaxDynamicSharedMemorySize, 16384 * 8);

    k_wtrans<<<576, 1024>>>(w_pre);

    for (int m = 0; m < 5; ++m) {
        int s = sidesA[m];
        int tiles = (s >> 3) * (s >> 3);
        dim3 grid(tiles, BB, 2);
        k_conv<<<grid, 256, convSmem>>>(fm[m], b_pre, s, HWsA[m], offsA[m]);
    }

    {
        dim3 grid((NPOS + 255) / 256, BB);
        k_proj<<<grid, 256>>>(w_proj, b_proj);
    }
    {
        dim3 grid(NCHUNK, BB);
        k_top1<<<grid, 512>>>();
    }
    k_top2<<<BB, 1024, 16384 * 8>>>();
    k_post<<<BB * KSEL, 256>>>(fm[0], fm[1], fm[2], fm[3], fm[4], w_post, b_post, out);
}

// round 4
// speedup vs baseline: 1.2689x; 1.2689x over previous
#include <cuda_runtime.h>
#include <cstdint>

typedef unsigned long long u64;
typedef unsigned int u32;

// ---------------- problem constants ----------------
#define BB 8
#define CC 256
#define NPOS 21824              // per-image positions across 5 maps
#define NANCH 196416            // NPOS * 9
#define NKEY 196608             // 48 * 4096 (padded)
#define KSEL 300
#define NCHUNK 48               // stage1 chunks of 4096 per image
#define NCAND (NCHUNK * KSEL)   // 14400 candidates per image

__device__ __constant__ int c_off[6] = {0, 16384, 20480, 21504, 21760, 21824};
__device__ __constant__ int c_mapS[5]   = {128, 64, 32, 16, 8};
__device__ __constant__ int c_mapOff[5] = {0, 16384, 20480, 21504, 21760};

// ---------------- device scratch ----------------
__device__ float g_relu[(size_t)174592 * 256];   // 8*21824 positions, NCHW per (b,map)
__device__ float g_wT[256 * 9 * 256];            // [ic][tap][oc]
__device__ u64   g_keys[(size_t)BB * NKEY];
__device__ u64   g_cand[(size_t)BB * NCAND];
__device__ int   g_sel[BB * KSEL];

// ---------------- f32x2 helpers ----------------
__device__ __forceinline__ u64 dup2(float x) {
    u64 r; asm("mov.b64 %0,{%1,%1};" : "=l"(r) : "f"(x)); return r;
}
__device__ __forceinline__ void ffma2(u64 &c, u64 a, u64 b) {
    asm("fma.rn.f32x2 %0,%1,%2,%3;" : "=l"(c) : "l"(a), "l"(b), "l"(c));
}
__device__ __forceinline__ void fadd2(u64 &c, u64 a) {
    asm("add.rn.f32x2 %0,%1,%2;" : "=l"(c) : "l"(c), "l"(a));
}
__device__ __forceinline__ float2 unpack2(u64 v) {
    float2 f; asm("mov.b64 {%0,%1},%2;" : "=f"(f.x), "=f"(f.y) : "l"(v)); return f;
}

// ---------------- kernel 0: weight transpose [oc][ic][t] -> [ic][t][oc] ----------------
__global__ void k_wtrans(const float* __restrict__ w_pre) {
    int i = blockIdx.x * 1024 + threadIdx.x;
    if (i >= 256 * 9 * 256) return;
    int oc = i & 255;
    int rest = i >> 8;
    int tap = rest % 9;
    int ic = rest / 9;
    g_wT[i] = w_pre[(oc * 256 + ic) * 9 + tap];
}

// ---------------- kernel 1: conv3x3 + bias + relu ----------------
// Merged over all 5 maps. Block: 8x8 spatial tile x 128 oc (z half). 256 threads.
// Thread: 2x2 pixels x 8 oc, f32x2 lanes = oc PAIR (weight = natural LDS.64, no dup).
// cp.async double-buffered input tile + weight chunk.
// Accumulation order per output: (ic 0..7, dy 0..2, dx 0..2) per chunk, 32 chunk folds
// -> bitwise identical to the previously passing kernel.

// smem float offsets
#define IB_FLOATS 960            // 8*10*12
#define WB_FLOATS 9216           // 8*9*128

__device__ __forceinline__ void issue_chunk(
    const float* __restrict__ fmB, int s, int HW, int ty0, int tx0,
    int cc, int zh, u32 ib_s, u32 wb_s, int tid)
{
    const float* fsrc = fmB + (size_t)(cc * 8) * HW;
    for (int idx = tid; idx < 800; idx += 256) {
        int ic = idx / 100;
        int rem = idx - ic * 100;
        int r = rem / 10;
        int c = rem - 10 * r;
        int gy = ty0 - 1 + r, gx = tx0 - 1 + c;
        bool ok = (gy >= 0) && (gy < s) && (gx >= 0) && (gx < s);
        const float* g = ok ? (fsrc + ic * HW + gy * s + gx) : fsrc;
        int sz = ok ? 4 : 0;
        u32 d = ib_s + (u32)(((ic * 10 + r) * 12 + c) * 4);
        asm volatile("cp.async.ca.shared.global [%0], [%1], 4, %2;"
                     :: "r"(d), "l"(g), "r"(sz) : "memory");
    }
    const float4* wbase = (const float4*)g_wT;
    for (int i = tid; i < 2304; i += 256) {     // 8*9*32 float4 (this oc-half)
        int icL = i / 288;
        int rem = i - icL * 288;
        int tap = rem >> 5;
        int q = rem & 31;
        const float4* g = wbase + (((size_t)(cc * 8 + icL) * 9 + tap) << 6) + (zh << 5) + q;
        u32 d = wb_s + (u32)(i * 16);
        asm volatile("cp.async.cg.shared.global [%0], [%1], 16;"
                     :: "r"(d), "l"(g) : "memory");
    }
}

#define LOADROW(dst, rr) { \
    dst[0] = dup2(ib[(rr)*12 + 0]); dst[1] = dup2(ib[(rr)*12 + 1]); \
    dst[2] = dup2(ib[(rr)*12 + 2]); dst[3] = dup2(ib[(rr)*12 + 3]); }

#define TAPROW(dy, top, bot) { \
    _Pragma("unroll") \
    for (int dx = 0; dx < 3; ++dx) { \
        const float* wp = wb + ((dy)*3 + dx) * 128; \
        u64 w0 = *(const u64*)(wp + 0); \
        u64 w1 = *(const u64*)(wp + 2); \
        u64 w2 = *(const u64*)(wp + 4); \
        u64 w3 = *(const u64*)(wp + 6); \
        ffma2(ch[0][0], top[dx],   w0); ffma2(ch[0][1], top[dx],   w1); \
        ffma2(ch[0][2], top[dx],   w2); ffma2(ch[0][3], top[dx],   w3); \
        ffma2(ch[1][0], top[dx+1], w0); ffma2(ch[1][1], top[dx+1], w1); \
        ffma2(ch[1][2], top[dx+1], w2); ffma2(ch[1][3], top[dx+1], w3); \
        ffma2(ch[2][0], bot[dx],   w0); ffma2(ch[2][1], bot[dx],   w1); \
        ffma2(ch[2][2], bot[dx],   w2); ffma2(ch[2][3], bot[dx],   w3); \
        ffma2(ch[3][0], bot[dx+1], w0); ffma2(ch[3][1], bot[dx+1], w1); \
        ffma2(ch[3][2], bot[dx+1], w2); ffma2(ch[3][3], bot[dx+1], w3); \
    } }

__global__ void __launch_bounds__(256, 2)
k_conv(const float* __restrict__ fm0, const float* __restrict__ fm1,
       const float* __restrict__ fm2, const float* __restrict__ fm3,
       const float* __restrict__ fm4, const float* __restrict__ b_pre) {
    extern __shared__ float sm[];
    float* ibuf[2] = {sm, sm + IB_FLOATS};
    float* wbuf[2] = {sm + 2 * IB_FLOATS, sm + 2 * IB_FLOATS + WB_FLOATS};
    const u32 smb = (u32)__cvta_generic_to_shared(sm);
    const u32 ibs[2] = {smb, smb + IB_FLOATS * 4};
    const u32 wbs[2] = {smb + 2 * IB_FLOATS * 4, smb + 2 * IB_FLOATS * 4 + WB_FLOATS * 4};

    const int tid = threadIdx.x;
    const int b = blockIdx.y;
    const int zh = blockIdx.z;

    // map lookup
    int bx = blockIdx.x, m, tile;
    if (bx < 256)      { m = 0; tile = bx; }
    else if (bx < 320) { m = 1; tile = bx - 256; }
    else if (bx < 336) { m = 2; tile = bx - 320; }
    else if (bx < 340) { m = 3; tile = bx - 336; }
    else               { m = 4; tile = bx - 340; }
    const int s = c_mapS[m];
    const int HW = s * s;
    const int posOff = c_mapOff[m];
    const float* fm = (m == 0) ? fm0 : (m == 1) ? fm1 : (m == 2) ? fm2 : (m == 3) ? fm3 : fm4;

    const int tilesX = s >> 3;
    const int ty0 = (tile / tilesX) << 3;
    const int tx0 = (tile % tilesX) << 3;

    const int pg = tid & 15;
    const int og = tid >> 4;              // 0..15 -> oc = zh*128 + og*8 + ..
    const int py = (pg >> 2) << 1;
    const int px = (pg & 3) << 1;

    const float* fmB = fm + (size_t)b * 256 * HW;

    u64 acc[4][4];
#pragma unroll
    for (int p = 0; p < 4; ++p)
#pragma unroll
        for (int j = 0; j < 4; ++j) acc[p][j] = 0ull;

    issue_chunk(fmB, s, HW, ty0, tx0, 0, zh, ibs[0], wbs[0], tid);
    asm volatile("cp.async.commit_group;" ::: "memory");

    for (int cc = 0; cc < 32; ++cc) {
        const int cur = cc & 1;
        asm volatile("cp.async.wait_group 0;" ::: "memory");
        __syncthreads();
        if (cc < 31) {
            issue_chunk(fmB, s, HW, ty0, tx0, cc + 1, zh, ibs[cur ^ 1], wbs[cur ^ 1], tid);
            asm volatile("cp.async.commit_group;" ::: "memory");
        }

        u64 ch[4][4];
#pragma unroll
        for (int p = 0; p < 4; ++p)
#pragma unroll
            for (int j = 0; j < 4; ++j) ch[p][j] = 0ull;

        const float* ibase = ibuf[cur] + py * 12 + px;
        const float* wbase2 = wbuf[cur] + og * 8;
#pragma unroll
        for (int ic = 0; ic < 8; ++ic) {
            const float* ib = ibase + ic * 120;
            const float* wb = wbase2 + ic * 1152;
            u64 rA[4], rB[4];
            LOADROW(rA, 0);
            LOADROW(rB, 1);
            TAPROW(0, rA, rB);
            LOADROW(rA, 2);
            TAPROW(1, rB, rA);
            LOADROW(rB, 3);
            TAPROW(2, rA, rB);
        }
#pragma unroll
        for (int p = 0; p < 4; ++p)
#pragma unroll
            for (int j = 0; j < 4; ++j) fadd2(acc[p][j], ch[p][j]);
    }

    // epilogue: bias + relu -> g_relu NCHW per (b,map)
    float* outB = g_relu + ((size_t)b * NPOS + posOff) * 256;
#pragma unroll
    for (int p = 0; p < 4; ++p) {
        int gy = ty0 + py + (p >> 1);
        int gx = tx0 + px + (p & 1);
#pragma unroll
        for (int j = 0; j < 4; ++j) {
            int oc = zh * 128 + og * 8 + 2 * j;
            float2 v = unpack2(acc[p][j]);
            outB[(size_t)oc * HW + gy * s + gx]       = fmaxf(v.x + b_pre[oc], 0.f);
            outB[(size_t)(oc + 1) * HW + gy * s + gx] = fmaxf(v.y + b_pre[oc + 1], 0.f);
        }
    }
}

// ---------------- kernel 2: 1x1 proj -> sigmoid -> sortable keys ----------------
__global__ void __launch_bounds__(256)
k_proj(const float* __restrict__ w_proj, const float* __restrict__ b_proj) {
    __shared__ float ws[9 * 256];
    const int tid = threadIdx.x;
    for (int i = tid; i < 2304; i += 256) ws[i] = w_proj[i];
    __syncthreads();

    const int b = blockIdx.y;
    const int p = blockIdx.x * 256 + tid;

    if (blockIdx.x == 0 && tid < (NKEY - NANCH))
        g_keys[(size_t)b * NKEY + NANCH + tid] = 0ull;
    if (p >= NPOS) return;

    int m, hw, HW;
    if (p < 16384)      { m = 0; hw = p;         HW = 16384; }
    else if (p < 20480) { m = 1; hw = p - 16384; HW = 4096;  }
    else if (p < 21504) { m = 2; hw = p - 20480; HW = 1024;  }
    else if (p < 21760) { m = 3; hw = p - 21504; HW = 256;   }
    else                { m = 4; hw = p - 21760; HW = 64;    }
    const int off = c_off[m];

    const float* rb = g_relu + ((size_t)b * NPOS + off) * 256 + hw;
    float sum[9];
#pragma unroll
    for (int a = 0; a < 9; ++a) sum[a] = 0.f;
    for (int c0 = 0; c0 < 256; c0 += 32) {
        float cs[9];
#pragma unroll
        for (int a = 0; a < 9; ++a) cs[a] = 0.f;
        for (int c = c0; c < c0 + 32; ++c) {
            float v = rb[(size_t)c * HW];
#pragma unroll
            for (int a = 0; a < 9; ++a) cs[a] += v * ws[a * 256 + c];
        }
#pragma unroll
        for (int a = 0; a < 9; ++a) sum[a] += cs[a];
    }
    u64* kb = g_keys + (size_t)b * NKEY + (size_t)p * 9;
#pragma unroll
    for (int a = 0; a < 9; ++a) {
        float logit = sum[a] + b_proj[a];
        float prob = 1.0f / (1.0f + expf(-logit));
        u32 pb = __float_as_uint(prob);
        u32 idx = (u32)(p * 9 + a);
        kb[a] = ((u64)pb << 32) | (u64)(0xFFFFFFFFu - idx);
    }
}

// ---------------- bitonic helpers (descending) ----------------
__device__ __forceinline__ void bitonic_step(u64* sk, int i, int j, int k) {
    int ixj = i | j;
    u64 a = sk[i], b = sk[ixj];
    bool dir = ((i & k) == 0);
    bool sw = dir ? (a < b) : (a > b);
    if (sw) { sk[i] = b; sk[ixj] = a; }
}

// ---------------- kernel 3: stage1 — sort each 4096 chunk, keep top 300 ----------------
__global__ void __launch_bounds__(512)
k_top1() {
    __shared__ u64 sk[4096];
    const int tid = threadIdx.x;
    const int blk = blockIdx.x;
    const int b = blockIdx.y;
    const u64* src = g_keys + (size_t)b * NKEY + (size_t)blk * 4096;
    for (int i = tid; i < 4096; i += 512) sk[i] = src[i];
    for (int k = 2; k <= 4096; k <<= 1) {
        for (int j = k >> 1; j > 0; j >>= 1) {
            __syncthreads();
            for (int t = tid; t < 2048; t += 512) {
                int i = ((t & ~(j - 1)) << 1) | (t & (j - 1));
                bitonic_step(sk, i, j, k);
            }
        }
    }
    __syncthreads();
    u64* dst = g_cand + ((size_t)b * NCHUNK + blk) * KSEL;
    for (int i = tid; i < KSEL; i += 512) dst[i] = sk[i];
}

// ---------------- kernel 4: stage2 — merge 14400 candidates per image ----------------
__global__ void __launch_bounds__(1024)
k_top2() {
    extern __shared__ u64 sk2[];   // 16384 keys = 128KB
    const int tid = threadIdx.x;
    const int b = blockIdx.x;
    const u64* src = g_cand + (size_t)b * NCAND;
    for (int i = tid; i < 16384; i += 1024) sk2[i] = (i < NCAND) ? src[i] : 0ull;
    for (int k = 2; k <= 16384; k <<= 1) {
        for (int j = k >> 1; j > 0; j >>= 1) {
            __syncthreads();
            for (int t = tid; t < 8192; t += 1024) {
                int i = ((t & ~(j - 1)) << 1) | (t & (j - 1));
                bitonic_step(sk2, i, j, k);
            }
        }
    }
    __syncthreads();
    if (tid < KSEL)
        g_sel[b * KSEL + tid] = (int)(0xFFFFFFFFu - (u32)(sk2[tid] & 0xFFFFFFFFull));
}

// ---------------- kernel 5: gather features + per-anchor 256x256 matvec ----------------
__global__ void __launch_bounds__(256)
k_post(const float* __restrict__ fm0, const float* __restrict__ fm1,
       const float* __restrict__ fm2, const float* __restrict__ fm3,
       const float* __restrict__ fm4, const float* __restrict__ w_post,
       const float* __restrict__ b_post, float* __restrict__ out) {
    __shared__ float x[256];
    const int n = blockIdx.x;
    const int tid = threadIdx.x;
    const int b = n / KSEL;
    const int anchor = g_sel[n];
    const int pos = anchor / 9;
    const int a = anchor - 9 * (anchor / 9);

    int m, hw, HW;
    if (pos < 16384)      { m = 0; hw = pos;         HW = 16384; }
    else if (pos < 20480) { m = 1; hw = pos - 16384; HW = 4096;  }
    else if (pos < 21504) { m = 2; hw = pos - 20480; HW = 1024;  }
    else if (pos < 21760) { m = 3; hw = pos - 21504; HW = 256;   }
    else                  { m = 4; hw = pos - 21760; HW = 64;    }
    const float* fm = (m == 0) ? fm0 : (m == 1) ? fm1 : (m == 2) ? fm2 : (m == 3) ? fm3 : fm4;

    x[tid] = fm[((size_t)b * 256 + tid) * HW + hw];
    __syncthreads();

    const float* W = w_post + (size_t)a * 65536;
    float accv = b_post[a * 256 + tid];
#pragma unroll 8
    for (int d = 0; d < 256; ++d)
        accv += x[d] * W[d * 256 + tid];
    out[(size_t)n * 256 + tid] = accv;
}

// ---------------- launch ----------------
extern "C" void kernel_launch(void* const* d_in, const int* in_sizes, int n_in,
                              void* d_out, int out_size) {
    const float* fm[5];
    for (int i = 0; i < 5; ++i) fm[i] = (const float*)d_in[i];
    const float* w_pre  = (const float*)d_in[5];
    const float* b_pre  = (const float*)d_in[6];
    const float* w_proj = (const float*)d_in[7];
    const float* b_proj = (const float*)d_in[8];
    const float* w_post = (const float*)d_in[9];
    const float* b_post = (const float*)d_in[10];
    float* out = (float*)d_out;

    const int convSmem = (2 * IB_FLOATS + 2 * WB_FLOATS) * 4;   // 81408 B
    cudaFuncSetAttribute(k_conv, cudaFuncAttributeMaxDynamicSharedMemorySize, convSmem);
    cudaFuncSetAttribute(k_top2, cudaFuncAttributeMaxDynamicSharedMemorySize, 16384 * 8);

    k_wtrans<<<576, 1024>>>(w_pre);

    {
        dim3 grid(341, BB, 2);   // 256+64+16+4+1 tiles across 5 maps
        k_conv<<<grid, 256, convSmem>>>(fm[0], fm[1], fm[2], fm[3], fm[4], b_pre);
    }
    {
        dim3 grid((NPOS + 255) / 256, BB);
        k_proj<<<grid, 256>>>(w_proj, b_proj);
    }
    {
        dim3 grid(NCHUNK, BB);
        k_top1<<<grid, 512>>>();
    }
    k_top2<<<BB, 1024, 16384 * 8>>>();
    k_post<<<BB * KSEL, 256>>>(fm[0], fm[1], fm[2], fm[3], fm[4], w_post, b_post, out);
}

// round 5
// speedup vs baseline: 1.4264x; 1.1242x over previous
#include <cuda_runtime.h>
#include <cstdint>

typedef unsigned long long u64;
typedef unsigned int u32;

// ---------------- problem constants ----------------
#define BB 8
#define CC 256
#define NPOS 21824              // per-image positions across 5 maps
#define NANCH 196416            // NPOS * 9
#define NKEY 196608             // 48 * 4096 (padded)
#define KSEL 300
#define NCHUNK 48               // stage1 chunks of 4096 per image
#define NCAND (NCHUNK * KSEL)   // 14400 candidates per image

__device__ __constant__ int c_off[6] = {0, 16384, 20480, 21504, 21760, 21824};
__device__ __constant__ int c_mapS[5]   = {128, 64, 32, 16, 8};
__device__ __constant__ int c_mapOff[5] = {0, 16384, 20480, 21504, 21760};

// ---------------- device scratch ----------------
__device__ float g_relu[(size_t)174592 * 256];   // 8*21824 positions, NCHW per (b,map)
__device__ float g_wT[256 * 9 * 256];            // [ic][tap][oc]
__device__ u64   g_keys[(size_t)BB * NKEY];
__device__ u64   g_cand[(size_t)BB * NCAND];
__device__ int   g_sel[BB * KSEL];

// ---------------- f32x2 helpers ----------------
__device__ __forceinline__ u64 dup2(float x) {
    u64 r; asm("mov.b64 %0,{%1,%1};" : "=l"(r) : "f"(x)); return r;
}
__device__ __forceinline__ void ffma2(u64 &c, u64 a, u64 b) {
    asm("fma.rn.f32x2 %0,%1,%2,%3;" : "=l"(c) : "l"(a), "l"(b), "l"(c));
}
__device__ __forceinline__ void fadd2(u64 &c, u64 a) {
    asm("add.rn.f32x2 %0,%1,%2;" : "=l"(c) : "l"(c), "l"(a));
}
__device__ __forceinline__ float2 unpack2(u64 v) {
    float2 f; asm("mov.b64 {%0,%1},%2;" : "=f"(f.x), "=f"(f.y) : "l"(v)); return f;
}

// ---------------- kernel 0: weight transpose [oc][ic][t] -> [ic][t][oc] ----------------
__global__ void k_wtrans(const float* __restrict__ w_pre) {
    int i = blockIdx.x * 1024 + threadIdx.x;
    if (i >= 256 * 9 * 256) return;
    int oc = i & 255;
    int rest = i >> 8;
    int tap = rest % 9;
    int ic = rest / 9;
    g_wT[i] = w_pre[(oc * 256 + ic) * 9 + tap];
}

// ---------------- kernel 1: conv3x3 + bias + relu ----------------
// Merged over all 5 maps. Block: 8x8 spatial tile x 128 oc (z half). 256 threads.
// Thread: 2x2 pixels x 8 oc (4 f32x2 oc-pair regs). cp.async double-buffered.
// All cp.async addressing precomputed once; per-chunk advance is a fixed stride.
// Accumulation order per output: (ic 0..7, dy 0..2, dx 0..2) per chunk, 32 chunk
// folds -> bitwise identical to the passing kernel (rel_err 0.0 preserved).

#define IB_FLOATS 960            // 8*10*12
#define WB_FLOATS 9216           // 8*9*128
#define W_CHUNK_BYTES 73728      // 8*9*256*4, g_wT stride per cc chunk

#define LOADROW(dst, rr) { \
    float2 a_ = *(const float2*)(ib + (rr)*12); \
    float2 b_ = *(const float2*)(ib + (rr)*12 + 2); \
    dst[0] = dup2(a_.x); dst[1] = dup2(a_.y); \
    dst[2] = dup2(b_.x); dst[3] = dup2(b_.y); }

#define TAPROW(dy, top, bot) { \
    _Pragma("unroll") \
    for (int dx = 0; dx < 3; ++dx) { \
        const ulonglong2* wp = (const ulonglong2*)(wb + ((dy)*3 + dx) * 128); \
        ulonglong2 wA = wp[0]; \
        ulonglong2 wB = wp[1]; \
        ffma2(ch[0][0], top[dx],   wA.x); ffma2(ch[0][1], top[dx],   wA.y); \
        ffma2(ch[0][2], top[dx],   wB.x); ffma2(ch[0][3], top[dx],   wB.y); \
        ffma2(ch[1][0], top[dx+1], wA.x); ffma2(ch[1][1], top[dx+1], wA.y); \
        ffma2(ch[1][2], top[dx+1], wB.x); ffma2(ch[1][3], top[dx+1], wB.y); \
        ffma2(ch[2][0], bot[dx],   wA.x); ffma2(ch[2][1], bot[dx],   wA.y); \
        ffma2(ch[2][2], bot[dx],   wB.x); ffma2(ch[2][3], bot[dx],   wB.y); \
        ffma2(ch[3][0], bot[dx+1], wA.x); ffma2(ch[3][1], bot[dx+1], wA.y); \
        ffma2(ch[3][2], bot[dx+1], wB.x); ffma2(ch[3][3], bot[dx+1], wB.y); \
    } }

__global__ void __launch_bounds__(256, 2)
k_conv(const float* __restrict__ fm0, const float* __restrict__ fm1,
       const float* __restrict__ fm2, const float* __restrict__ fm3,
       const float* __restrict__ fm4, const float* __restrict__ b_pre) {
    extern __shared__ float sm[];
    float* ibuf[2] = {sm, sm + IB_FLOATS};
    float* wbuf[2] = {sm + 2 * IB_FLOATS, sm + 2 * IB_FLOATS + WB_FLOATS};
    const u32 smb = (u32)__cvta_generic_to_shared(sm);
    const u32 ibs[2] = {smb, smb + IB_FLOATS * 4};
    const u32 wbs[2] = {smb + 2 * IB_FLOATS * 4, smb + 2 * IB_FLOATS * 4 + WB_FLOATS * 4};

    const int tid = threadIdx.x;
    const int b = blockIdx.y;
    const int zh = blockIdx.z;

    // map lookup
    int bx = blockIdx.x, m, tile;
    if (bx < 256)      { m = 0; tile = bx; }
    else if (bx < 320) { m = 1; tile = bx - 256; }
    else if (bx < 336) { m = 2; tile = bx - 320; }
    else if (bx < 340) { m = 3; tile = bx - 336; }
    else               { m = 4; tile = bx - 340; }
    const int s = c_mapS[m];
    const int HW = s * s;
    const int posOff = c_mapOff[m];
    const float* fm = (m == 0) ? fm0 : (m == 1) ? fm1 : (m == 2) ? fm2 : (m == 3) ? fm3 : fm4;

    const int tilesX = s >> 3;
    const int ty0 = (tile / tilesX) << 3;
    const int tx0 = (tile % tilesX) << 3;

    const int pg = tid & 15;
    const int og = tid >> 4;              // 0..15 -> oc = zh*128 + og*8 + ..
    const int py = (pg >> 2) << 1;
    const int px = (pg & 3) << 1;

    const char* fb = (const char*)(fm + (size_t)b * 256 * HW);

    // ---- precompute cp.async descriptors (loop-invariant) ----
    // inputs: 800 elements -> thread handles idx = tid + k*256, k=0..3
    bool in_act[4];
    u32  in_so[4];       // smem byte offset within ibuf
    u32  in_go[4];       // gmem byte offset within fmB (chunk 0)
    u32  in_sz[4];       // 4 = real load, 0 = zero-fill (halo OOB)
#pragma unroll
    for (int k = 0; k < 4; ++k) {
        int idx = tid + (k << 8);
        in_act[k] = (idx < 800);
        int ii = in_act[k] ? idx : 0;
        int ic = ii / 100;
        int rem = ii - ic * 100;
        int r = rem / 10;
        int c = rem - 10 * r;
        int gy = ty0 - 1 + r, gx = tx0 - 1 + c;
        bool ok = (gy >= 0) && (gy < s) && (gx >= 0) && (gx < s);
        in_so[k] = (u32)(((ic * 10 + r) * 12 + c) * 4);
        in_go[k] = ok ? (u32)((ic * HW + gy * s + gx) * 4) : 0u;
        in_sz[k] = ok ? 4u : 0u;
    }
    // weights: 2304 float4 -> thread handles i = tid + k*256, k=0..8
    u32 w_so[9], w_go[9];
#pragma unroll
    for (int k = 0; k < 9; ++k) {
        int i = tid + (k << 8);
        int icL = i / 288;
        int rem = i - icL * 288;
        int tap = rem >> 5;
        int q = rem & 31;
        w_so[k] = (u32)(i * 16);
        w_go[k] = (u32)(((((icL * 9 + tap) << 6) + (zh << 5) + q)) * 16);
    }
    const char* wtb = (const char*)g_wT;

    u64 acc[4][4];
#pragma unroll
    for (int p = 0; p < 4; ++p)
#pragma unroll
        for (int j = 0; j < 4; ++j) acc[p][j] = 0ull;

    // issue chunk 0
    {
        const char* f = fb;
#pragma unroll
        for (int k = 0; k < 4; ++k) if (in_act[k])
            asm volatile("cp.async.ca.shared.global [%0], [%1], 4, %2;"
                         :: "r"(ibs[0] + in_so[k]), "l"(f + in_go[k]), "r"(in_sz[k]) : "memory");
#pragma unroll
        for (int k = 0; k < 9; ++k)
            asm volatile("cp.async.cg.shared.global [%0], [%1], 16;"
                         :: "r"(wbs[0] + w_so[k]), "l"(wtb + w_go[k]) : "memory");
        asm volatile("cp.async.commit_group;" ::: "memory");
    }

    const u32 inStride = (u32)(8 * HW * 4);

    for (int cc = 0; cc < 32; ++cc) {
        const int cur = cc & 1;
        asm volatile("cp.async.wait_group 0;" ::: "memory");
        __syncthreads();
        if (cc < 31) {
            const char* f = fb + (size_t)(cc + 1) * inStride;
            const char* w = wtb + (size_t)(cc + 1) * W_CHUNK_BYTES;
            const u32 ibS = ibs[cur ^ 1], wbS = wbs[cur ^ 1];
#pragma unroll
            for (int k = 0; k < 4; ++k) if (in_act[k])
                asm volatile("cp.async.ca.shared.global [%0], [%1], 4, %2;"
                             :: "r"(ibS + in_so[k]), "l"(f + in_go[k]), "r"(in_sz[k]) : "memory");
#pragma unroll
            for (int k = 0; k < 9; ++k)
                asm volatile("cp.async.cg.shared.global [%0], [%1], 16;"
                             :: "r"(wbS + w_so[k]), "l"(w + w_go[k]) : "memory");
            asm volatile("cp.async.commit_group;" ::: "memory");
        }

        u64 ch[4][4];
#pragma unroll
        for (int p = 0; p < 4; ++p)
#pragma unroll
            for (int j = 0; j < 4; ++j) ch[p][j] = 0ull;

        const float* ibase = ibuf[cur] + py * 12 + px;
        const float* wbase2 = wbuf[cur] + og * 8;
#pragma unroll
        for (int ic = 0; ic < 8; ++ic) {
            const float* ib = ibase + ic * 120;
            const float* wb = wbase2 + ic * 1152;
            u64 rA[4], rB[4];
            LOADROW(rA, 0);
            LOADROW(rB, 1);
            TAPROW(0, rA, rB);
            LOADROW(rA, 2);
            TAPROW(1, rB, rA);
            LOADROW(rB, 3);
            TAPROW(2, rA, rB);
        }
#pragma unroll
        for (int p = 0; p < 4; ++p)
#pragma unroll
            for (int j = 0; j < 4; ++j) fadd2(acc[p][j], ch[p][j]);
    }

    // epilogue: bias + relu -> g_relu NCHW per (b,map)
    float* outB = g_relu + ((size_t)b * NPOS + posOff) * 256;
#pragma unroll
    for (int p = 0; p < 4; ++p) {
        int gy = ty0 + py + (p >> 1);
        int gx = tx0 + px + (p & 1);
#pragma unroll
        for (int j = 0; j < 4; ++j) {
            int oc = zh * 128 + og * 8 + 2 * j;
            float2 v = unpack2(acc[p][j]);
            outB[(size_t)oc * HW + gy * s + gx]       = fmaxf(v.x + b_pre[oc], 0.f);
            outB[(size_t)(oc + 1) * HW + gy * s + gx] = fmaxf(v.y + b_pre[oc + 1], 0.f);
        }
    }
}

// ---------------- kernel 2: 1x1 proj -> sigmoid -> sortable keys ----------------
__global__ void __launch_bounds__(256)
k_proj(const float* __restrict__ w_proj, const float* __restrict__ b_proj) {
    __shared__ float ws[9 * 256];
    const int tid = threadIdx.x;
    for (int i = tid; i < 2304; i += 256) ws[i] = w_proj[i];
    __syncthreads();

    const int b = blockIdx.y;
    const int p = blockIdx.x * 256 + tid;

    if (blockIdx.x == 0 && tid < (NKEY - NANCH))
        g_keys[(size_t)b * NKEY + NANCH + tid] = 0ull;
    if (p >= NPOS) return;

    int m, hw, HW;
    if (p < 16384)      { m = 0; hw = p;         HW = 16384; }
    else if (p < 20480) { m = 1; hw = p - 16384; HW = 4096;  }
    else if (p < 21504) { m = 2; hw = p - 20480; HW = 1024;  }
    else if (p < 21760) { m = 3; hw = p - 21504; HW = 256;   }
    else                { m = 4; hw = p - 21760; HW = 64;    }
    const int off = c_off[m];

    const float* rb = g_relu + ((size_t)b * NPOS + off) * 256 + hw;
    float sum[9];
#pragma unroll
    for (int a = 0; a < 9; ++a) sum[a] = 0.f;
    for (int c0 = 0; c0 < 256; c0 += 32) {
        float cs[9];
#pragma unroll
        for (int a = 0; a < 9; ++a) cs[a] = 0.f;
        for (int c = c0; c < c0 + 32; ++c) {
            float v = rb[(size_t)c * HW];
#pragma unroll
            for (int a = 0; a < 9; ++a) cs[a] += v * ws[a * 256 + c];
        }
#pragma unroll
        for (int a = 0; a < 9; ++a) sum[a] += cs[a];
    }
    u64* kb = g_keys + (size_t)b * NKEY + (size_t)p * 9;
#pragma unroll
    for (int a = 0; a < 9; ++a) {
        float logit = sum[a] + b_proj[a];
        float prob = 1.0f / (1.0f + expf(-logit));
        u32 pb = __float_as_uint(prob);
        u32 idx = (u32)(p * 9 + a);
        kb[a] = ((u64)pb << 32) | (u64)(0xFFFFFFFFu - idx);
    }
}

// ---------------- bitonic helpers (descending) ----------------
__device__ __forceinline__ void bitonic_step(u64* sk, int i, int j, int k) {
    int ixj = i | j;
    u64 a = sk[i], b = sk[ixj];
    bool dir = ((i & k) == 0);
    bool sw = dir ? (a < b) : (a > b);
    if (sw) { sk[i] = b; sk[ixj] = a; }
}

// ---------------- kernel 3: stage1 — sort each 4096 chunk, keep top 300 ----------------
__global__ void __launch_bounds__(512)
k_top1() {
    __shared__ u64 sk[4096];
    const int tid = threadIdx.x;
    const int blk = blockIdx.x;
    const int b = blockIdx.y;
    const u64* src = g_keys + (size_t)b * NKEY + (size_t)blk * 4096;
    for (int i = tid; i < 4096; i += 512) sk[i] = src[i];
    for (int k = 2; k <= 4096; k <<= 1) {
        for (int j = k >> 1; j > 0; j >>= 1) {
            __syncthreads();
            for (int t = tid; t < 2048; t += 512) {
                int i = ((t & ~(j - 1)) << 1) | (t & (j - 1));
                bitonic_step(sk, i, j, k);
            }
        }
    }
    __syncthreads();
    u64* dst = g_cand + ((size_t)b * NCHUNK + blk) * KSEL;
    for (int i = tid; i < KSEL; i += 512) dst[i] = sk[i];
}

// ---------------- kernel 4: stage2 — merge 14400 candidates per image ----------------
__global__ void __launch_bounds__(1024)
k_top2() {
    extern __shared__ u64 sk2[];   // 16384 keys = 128KB
    const int tid = threadIdx.x;
    const int b = blockIdx.x;
    const u64* src = g_cand + (size_t)b * NCAND;
    for (int i = tid; i < 16384; i += 1024) sk2[i] = (i < NCAND) ? src[i] : 0ull;
    for (int k = 2; k <= 16384; k <<= 1) {
        for (int j = k >> 1; j > 0; j >>= 1) {
            __syncthreads();
            for (int t = tid; t < 8192; t += 1024) {
                int i = ((t & ~(j - 1)) << 1) | (t & (j - 1));
                bitonic_step(sk2, i, j, k);
            }
        }
    }
    __syncthreads();
    if (tid < KSEL)
        g_sel[b * KSEL + tid] = (int)(0xFFFFFFFFu - (u32)(sk2[tid] & 0xFFFFFFFFull));
}

// ---------------- kernel 5: gather features + per-anchor 256x256 matvec ----------------
__global__ void __launch_bounds__(256)
k_post(const float* __restrict__ fm0, const float* __restrict__ fm1,
       const float* __restrict__ fm2, const float* __restrict__ fm3,
       const float* __restrict__ fm4, const float* __restrict__ w_post,
       const float* __restrict__ b_post, float* __restrict__ out) {
    __shared__ float x[256];
    const int n = blockIdx.x;
    const int tid = threadIdx.x;
    const int b = n / KSEL;
    const int anchor = g_sel[n];
    const int pos = anchor / 9;
    const int a = anchor - 9 * (anchor / 9);

    int m, hw, HW;
    if (pos < 16384)      { m = 0; hw = pos;         HW = 16384; }
    else if (pos < 20480) { m = 1; hw = pos - 16384; HW = 4096;  }
    else if (pos < 21504) { m = 2; hw = pos - 20480; HW = 1024;  }
    else if (pos < 21760) { m = 3; hw = pos - 21504; HW = 256;   }
    else                  { m = 4; hw = pos - 21760; HW = 64;    }
    const float* fm = (m == 0) ? fm0 : (m == 1) ? fm1 : (m == 2) ? fm2 : (m == 3) ? fm3 : fm4;

    x[tid] = fm[((size_t)b * 256 + tid) * HW + hw];
    __syncthreads();

    const float* W = w_post + (size_t)a * 65536;
    float accv = b_post[a * 256 + tid];
#pragma unroll 8
    for (int d = 0; d < 256; ++d)
        accv += x[d] * W[d * 256 + tid];
    out[(size_t)n * 256 + tid] = accv;
}

// ---------------- launch ----------------
extern "C" void kernel_launch(void* const* d_in, const int* in_sizes, int n_in,
                              void* d_out, int out_size) {
    const float* fm[5];
    for (int i = 0; i < 5; ++i) fm[i] = (const float*)d_in[i];
    const float* w_pre  = (const float*)d_in[5];
    const float* b_pre  = (const float*)d_in[6];
    const float* w_proj = (const float*)d_in[7];
    const float* b_proj = (const float*)d_in[8];
    const float* w_post = (const float*)d_in[9];
    const float* b_post = (const float*)d_in[10];
    float* out = (float*)d_out;

    const int convSmem = (2 * IB_FLOATS + 2 * WB_FLOATS) * 4;   // 81408 B
    cudaFuncSetAttribute(k_conv, cudaFuncAttributeMaxDynamicSharedMemorySize, convSmem);
    cudaFuncSetAttribute(k_top2, cudaFuncAttributeMaxDynamicSharedMemorySize, 16384 * 8);

    k_wtrans<<<576, 1024>>>(w_pre);

    {
        dim3 grid(341, BB, 2);   // 256+64+16+4+1 tiles across 5 maps
        k_conv<<<grid, 256, convSmem>>>(fm[0], fm[1], fm[2], fm[3], fm[4], b_pre);
    }
    {
        dim3 grid((NPOS + 255) / 256, BB);
        k_proj<<<grid, 256>>>(w_proj, b_proj);
    }
    {
        dim3 grid(NCHUNK, BB);
        k_top1<<<grid, 512>>>();
    }
    k_top2<<<BB, 1024, 16384 * 8>>>();
    k_post<<<BB * KSEL, 256>>>(fm[0], fm[1], fm[2], fm[3], fm[4], w_post, b_post, out);
}